// round 1
// baseline (speedup 1.0000x reference)
#include <cuda_runtime.h>
#include <cstdint>

#define N_TOKENS 8192
#define D_IN 2048
#define HIDDEN 2048
#define N_EXPERTS 8
#define TOPK 2

#define BM 128
#define BN 128
#define BK 32
#define SPAD 8  // smem row stride = 128 + 8 = 136 -> conflict-free fragment gathers

// ---------------- scratch (no allocations allowed) ----------------
__device__ int   g_counts[N_EXPERTS];
__device__ int   g_tokens[N_EXPERTS * N_TOKENS];
__device__ float g_wts[N_EXPERTS * N_TOKENS];

// ---------------- helpers ----------------
__device__ __forceinline__ uint32_t f2tf32(float f) {
    uint32_t r;
    asm("cvt.rna.tf32.f32 %0, %1;" : "=r"(r) : "f"(f));
    return r;
}

__device__ __forceinline__ void mma_tf32(float c[4], const uint32_t a[4], const uint32_t b[2]) {
    asm volatile(
        "mma.sync.aligned.m16n8k8.row.col.f32.tf32.tf32.f32 "
        "{%0,%1,%2,%3}, {%4,%5,%6,%7}, {%8,%9}, {%0,%1,%2,%3};"
        : "+f"(c[0]), "+f"(c[1]), "+f"(c[2]), "+f"(c[3])
        : "r"(a[0]), "r"(a[1]), "r"(a[2]), "r"(a[3]), "r"(b[0]), "r"(b[1]));
}

// ---------------- kernel 0: zero output + counters ----------------
__global__ void zero_kernel(float* __restrict__ out, int n4) {
    float4 z = make_float4(0.f, 0.f, 0.f, 0.f);
    for (int i = blockIdx.x * blockDim.x + threadIdx.x; i < n4; i += gridDim.x * blockDim.x)
        reinterpret_cast<float4*>(out)[i] = z;
    if (blockIdx.x == 0 && threadIdx.x < N_EXPERTS) g_counts[threadIdx.x] = 0;
}

// ---------------- kernel 1: gating + softmax + top-2 + routing ----------------
// one warp per token
__global__ void gating_kernel(const float* __restrict__ x,
                              const float* __restrict__ Wg,
                              const float* __restrict__ bg) {
    int warp = threadIdx.x >> 5;
    int lane = threadIdx.x & 31;
    int n = blockIdx.x * 8 + warp;
    if (n >= N_TOKENS) return;

    float acc[8];
#pragma unroll
    for (int e = 0; e < 8; e++) acc[e] = 0.f;

    const float* xr = x + (size_t)n * D_IN;
    for (int i = lane; i < D_IN; i += 32) {
        float xv = xr[i];
        float4 w0 = *reinterpret_cast<const float4*>(Wg + (size_t)i * 8);
        float4 w1 = *reinterpret_cast<const float4*>(Wg + (size_t)i * 8 + 4);
        acc[0] += xv * w0.x; acc[1] += xv * w0.y; acc[2] += xv * w0.z; acc[3] += xv * w0.w;
        acc[4] += xv * w1.x; acc[5] += xv * w1.y; acc[6] += xv * w1.z; acc[7] += xv * w1.w;
    }
#pragma unroll
    for (int off = 16; off > 0; off >>= 1) {
#pragma unroll
        for (int e = 0; e < 8; e++)
            acc[e] += __shfl_down_sync(0xffffffffu, acc[e], off);
    }

    if (lane == 0) {
        float l[8];
#pragma unroll
        for (int e = 0; e < 8; e++) l[e] = acc[e] + bg[e];
        float mx = l[0];
#pragma unroll
        for (int e = 1; e < 8; e++) mx = fmaxf(mx, l[e]);
        float p[8], s = 0.f;
#pragma unroll
        for (int e = 0; e < 8; e++) { p[e] = __expf(l[e] - mx); }
        // use accurate expf for parity with reference softmax
#pragma unroll
        for (int e = 0; e < 8; e++) { p[e] = expf(l[e] - mx); s += p[e]; }

        // top-1: strict > keeps lowest index on ties (matches lax.top_k)
        int i1 = 0;
#pragma unroll
        for (int e = 1; e < 8; e++) if (l[e] > l[i1]) i1 = e;
        // top-2: lowest-index argmax excluding i1
        int i2 = (i1 == 0) ? 1 : 0;
#pragma unroll
        for (int e = 0; e < 8; e++) if (e != i1 && l[e] > l[i2]) i2 = e;

        float w1 = p[i1] / s;
        float w2 = p[i2] / s;

        int p1 = atomicAdd(&g_counts[i1], 1);
        g_tokens[i1 * N_TOKENS + p1] = n;
        g_wts[i1 * N_TOKENS + p1] = w1;
        int p2 = atomicAdd(&g_counts[i2], 1);
        g_tokens[i2 * N_TOKENS + p2] = n;
        g_wts[i2 * N_TOKENS + p2] = w2;
    }
}

// ---------------- kernel 2: grouped gathered GEMM (tf32 mma.sync) ----------------
// grid: (tiles_m=64, tiles_n=16, experts=8); blocks past an expert's count exit early.
__global__ __launch_bounds__(256, 2)
void moe_gemm_kernel(const float* __restrict__ x,
                     const float* __restrict__ We,
                     const float* __restrict__ be,
                     float* __restrict__ out) {
    const int e = blockIdx.z;
    const int cnt = g_counts[e];
    const int m0 = blockIdx.x * BM;
    if (m0 >= cnt) return;
    const int n0 = blockIdx.y * BN;

    __shared__ uint32_t sA[BK][BM + SPAD];  // [k][m], tf32 bits
    __shared__ uint32_t sB[BK][BN + SPAD];  // [k][n], tf32 bits

    const float* Wexp = We + (size_t)e * D_IN * HIDDEN;
    const int*   toks = g_tokens + e * N_TOKENS;
    const float* wts  = g_wts + e * N_TOKENS;

    const int tid = threadIdx.x;
    const int warp = tid >> 5, lane = tid & 31;
    const int wm = warp >> 2, wn = warp & 3;       // 2 x 4 warp grid
    const int lr = lane >> 2, lc = lane & 3;

    float c[4][4][4];
#pragma unroll
    for (int mt = 0; mt < 4; mt++)
#pragma unroll
        for (int nt = 0; nt < 4; nt++)
#pragma unroll
            for (int i = 0; i < 4; i++) c[mt][nt][i] = 0.f;

    // A staging assignment: thread -> (row, k4); 32 rows per pass, 4 passes
    const int a_row = tid >> 3;        // 0..31
    const int a_k   = (tid & 7) * 4;   // 0,4,...,28
    int  a_tok[4];
    bool a_ok[4];
#pragma unroll
    for (int p = 0; p < 4; p++) {
        int gr = m0 + p * 32 + a_row;
        a_ok[p]  = (gr < cnt);
        a_tok[p] = a_ok[p] ? toks[gr] : 0;
    }
    // B staging assignment: thread -> (k, n4); 8 k-rows per pass, 4 passes
    const int b_k = tid >> 5;          // 0..7
    const int b_n = (tid & 31) * 4;    // 0..124

    for (int k0 = 0; k0 < D_IN; k0 += BK) {
        __syncthreads();
        // stage A (gathered, transpose to [k][m], cvt to tf32)
#pragma unroll
        for (int p = 0; p < 4; p++) {
            float4 v = make_float4(0.f, 0.f, 0.f, 0.f);
            if (a_ok[p])
                v = *reinterpret_cast<const float4*>(x + (size_t)a_tok[p] * D_IN + k0 + a_k);
            int r = p * 32 + a_row;
            sA[a_k + 0][r] = f2tf32(v.x);
            sA[a_k + 1][r] = f2tf32(v.y);
            sA[a_k + 2][r] = f2tf32(v.z);
            sA[a_k + 3][r] = f2tf32(v.w);
        }
        // stage B ([k][n], cvt to tf32, vector store)
#pragma unroll
        for (int p = 0; p < 4; p++) {
            int k = p * 8 + b_k;
            float4 v = *reinterpret_cast<const float4*>(Wexp + (size_t)(k0 + k) * HIDDEN + n0 + b_n);
            uint4 u;
            u.x = f2tf32(v.x); u.y = f2tf32(v.y); u.z = f2tf32(v.z); u.w = f2tf32(v.w);
            *reinterpret_cast<uint4*>(&sB[k][b_n]) = u;
        }
        __syncthreads();

#pragma unroll
        for (int ks = 0; ks < 4; ks++) {
            const int kb = ks * 8;
            uint32_t a[4][4], b[4][2];
#pragma unroll
            for (int mt = 0; mt < 4; mt++) {
                int m = wm * 64 + mt * 16 + lr;
                a[mt][0] = sA[kb + lc][m];
                a[mt][1] = sA[kb + lc][m + 8];
                a[mt][2] = sA[kb + lc + 4][m];
                a[mt][3] = sA[kb + lc + 4][m + 8];
            }
#pragma unroll
            for (int nt = 0; nt < 4; nt++) {
                int nn = wn * 32 + nt * 8 + lr;
                b[nt][0] = sB[kb + lc][nn];
                b[nt][1] = sB[kb + lc + 4][nn];
            }
#pragma unroll
            for (int mt = 0; mt < 4; mt++)
#pragma unroll
                for (int nt = 0; nt < 4; nt++)
                    mma_tf32(c[mt][nt], a[mt], b[nt]);
        }
    }

    // epilogue: out[tok, col] += w * (acc + be[e, col])
    const float* bee = be + (size_t)e * HIDDEN;
#pragma unroll
    for (int mt = 0; mt < 4; mt++) {
#pragma unroll
        for (int half = 0; half < 2; half++) {
            int gr = m0 + wm * 64 + mt * 16 + lr + half * 8;
            if (gr < cnt) {
                int tok = toks[gr];
                float w = wts[gr];
                float* orow = out + (size_t)tok * HIDDEN;
#pragma unroll
                for (int nt = 0; nt < 4; nt++) {
                    int col = n0 + wn * 32 + nt * 8 + 2 * lc;
                    float v0 = c[mt][nt][half * 2 + 0];
                    float v1 = c[mt][nt][half * 2 + 1];
                    atomicAdd(&orow[col],     w * (v0 + bee[col]));
                    atomicAdd(&orow[col + 1], w * (v1 + bee[col + 1]));
                }
            }
        }
    }
}

// ---------------- launch ----------------
extern "C" void kernel_launch(void* const* d_in, const int* in_sizes, int n_in,
                              void* d_out, int out_size) {
    const float* x  = (const float*)d_in[0];
    const float* Wg = (const float*)d_in[1];
    const float* bg = (const float*)d_in[2];
    const float* We = (const float*)d_in[3];
    const float* be = (const float*)d_in[4];
    float* out = (float*)d_out;

    zero_kernel<<<2048, 256>>>(out, out_size / 4);
    gating_kernel<<<N_TOKENS / 8, 256>>>(x, Wg, bg);
    dim3 grid(N_TOKENS / BM, HIDDEN / BN, N_EXPERTS);
    moe_gemm_kernel<<<grid, 256>>>(x, We, be, out);
}

// round 5
// speedup vs baseline: 2.5014x; 2.5014x over previous
#include <cuda_runtime.h>
#include <cuda_fp16.h>
#include <cstdint>

#define N_TOKENS 8192
#define D_IN 2048
#define HIDDEN 2048
#define N_EXPERTS 8
#define NK16 (D_IN / 16)     // 128 k16 blocks
#define NCHUNK (D_IN / 32)   // 64 k-chunks of 32

// ---------------- scratch (device globals; no allocation) ----------------
__device__ int   g_counts[N_EXPERTS];
__device__ int   g_tokens[N_EXPERTS * N_TOKENS];
__device__ float g_wts[N_EXPERTS * N_TOKENS];
// A in fragment layout: [e][m16(512)][k16(128)][lane(32)] x 16B
__device__ uint4 g_A[(size_t)N_EXPERTS * 512 * NK16 * 32];
// B in fragment layout: [e][n16(128)][k16(128)][lane(32)] x 16B
__device__ uint4 g_B[(size_t)N_EXPERTS * 128 * NK16 * 32];

// ---------------- helpers ----------------
__device__ __forceinline__ void mma16816(float c[4], uint4 a, uint32_t b0, uint32_t b1) {
    asm volatile(
        "mma.sync.aligned.m16n8k16.row.col.f32.f16.f16.f32 "
        "{%0,%1,%2,%3},{%4,%5,%6,%7},{%8,%9},{%0,%1,%2,%3};"
        : "+f"(c[0]), "+f"(c[1]), "+f"(c[2]), "+f"(c[3])
        : "r"(a.x), "r"(a.y), "r"(a.z), "r"(a.w), "r"(b0), "r"(b1));
}
__device__ __forceinline__ uint32_t h2u(__half2 h) { return *reinterpret_cast<uint32_t*>(&h); }

#define CP16(dst_u32, src_ptr) \
    asm volatile("cp.async.ca.shared.global [%0], [%1], 16;" :: "r"(dst_u32), "l"(src_ptr))

// ---------------- kernel 0: zero output + counters ----------------
__global__ void zero_kernel(float* __restrict__ out, int n4) {
    float4 z = make_float4(0.f, 0.f, 0.f, 0.f);
    for (int i = blockIdx.x * blockDim.x + threadIdx.x; i < n4; i += gridDim.x * blockDim.x)
        reinterpret_cast<float4*>(out)[i] = z;
    if (blockIdx.x == 0 && threadIdx.x < N_EXPERTS) g_counts[threadIdx.x] = 0;
}

// ---------------- kernel 1: gating + softmax + top-2 routing ----------------
__global__ void gating_kernel(const float* __restrict__ x,
                              const float* __restrict__ Wg,
                              const float* __restrict__ bg) {
    int warp = threadIdx.x >> 5;
    int lane = threadIdx.x & 31;
    int n = blockIdx.x * 8 + warp;
    if (n >= N_TOKENS) return;

    float acc[8];
#pragma unroll
    for (int e = 0; e < 8; e++) acc[e] = 0.f;

    const float* xr = x + (size_t)n * D_IN;
    for (int i = lane; i < D_IN; i += 32) {
        float xv = xr[i];
        float4 w0 = *reinterpret_cast<const float4*>(Wg + (size_t)i * 8);
        float4 w1 = *reinterpret_cast<const float4*>(Wg + (size_t)i * 8 + 4);
        acc[0] += xv * w0.x; acc[1] += xv * w0.y; acc[2] += xv * w0.z; acc[3] += xv * w0.w;
        acc[4] += xv * w1.x; acc[5] += xv * w1.y; acc[6] += xv * w1.z; acc[7] += xv * w1.w;
    }
#pragma unroll
    for (int off = 16; off > 0; off >>= 1)
#pragma unroll
        for (int e = 0; e < 8; e++)
            acc[e] += __shfl_down_sync(0xffffffffu, acc[e], off);

    if (lane == 0) {
        float l[8];
#pragma unroll
        for (int e = 0; e < 8; e++) l[e] = acc[e] + bg[e];
        float mx = l[0];
#pragma unroll
        for (int e = 1; e < 8; e++) mx = fmaxf(mx, l[e]);
        float p[8], s = 0.f;
#pragma unroll
        for (int e = 0; e < 8; e++) { p[e] = expf(l[e] - mx); s += p[e]; }

        int i1 = 0;
#pragma unroll
        for (int e = 1; e < 8; e++) if (l[e] > l[i1]) i1 = e;
        int i2 = (i1 == 0) ? 1 : 0;
#pragma unroll
        for (int e = 0; e < 8; e++) if (e != i1 && l[e] > l[i2]) i2 = e;

        int p1 = atomicAdd(&g_counts[i1], 1);
        g_tokens[i1 * N_TOKENS + p1] = n;
        g_wts[i1 * N_TOKENS + p1] = p[i1] / s;
        int p2 = atomicAdd(&g_counts[i2], 1);
        g_tokens[i2 * N_TOKENS + p2] = n;
        g_wts[i2 * N_TOKENS + p2] = p[i2] / s;
    }
}

// ---------------- kernel 2: format We -> g_B fragment layout ----------------
// block: (n64, k128, e). Reads row-pairs along k, packs half2 (k even low).
__global__ void format_B(const float* __restrict__ We) {
    __shared__ uint32_t sb[4 * 8 * 32 * 4];  // 16KB: [ln16][lk16][lane][4 slots]
    const int e = blockIdx.z, n0 = blockIdx.x * 64, k0 = blockIdx.y * 128;
    const float* W = We + (size_t)e * D_IN * HIDDEN;
    const int t = threadIdx.x;
#pragma unroll
    for (int it = 0; it < 4; it++) {
        int lin = it * 256 + t;          // 0..1023
        int rp = lin >> 4;               // 0..63 (k row-pair)
        int c4 = lin & 15;               // float4 along n
        float4 v0 = *reinterpret_cast<const float4*>(W + (size_t)(k0 + 2 * rp) * HIDDEN + n0 + c4 * 4);
        float4 v1 = *reinterpret_cast<const float4*>(W + (size_t)(k0 + 2 * rp + 1) * HIDDEN + n0 + c4 * 4);
        float a0[4] = {v0.x, v0.y, v0.z, v0.w};
        float a1[4] = {v1.x, v1.y, v1.z, v1.w};
        int c = rp & 3;                  // (k&7)>>1
        int reg = (rp >> 2) & 1;         // (k&15)>=8
        int lk16 = rp >> 3;
#pragma unroll
        for (int j = 0; j < 4; j++) {
            int n = c4 * 4 + j;
            int ln16 = n >> 4, nn = n & 15;
            int lane = (nn & 7) * 4 + c;
            int slot = ((nn >> 3) << 1) | reg;
            sb[((((ln16 * 8 + lk16) * 32) + lane) << 2) + slot] = h2u(__floats2half2_rn(a0[j], a1[j]));
        }
    }
    __syncthreads();
    uint4* gdst = g_B + ((size_t)(e * 128 + (n0 >> 4)) * NK16 + (k0 >> 4)) * 32;
#pragma unroll
    for (int i = 0; i < 4; i++) {
        int lin = i * 256 + t;
        int ln16 = lin >> 8, lk16 = (lin >> 5) & 7, lane = lin & 31;
        gdst[((size_t)ln16 * NK16 + lk16) * 32 + lane] = reinterpret_cast<uint4*>(sb)[lin];
    }
}

// ---------------- kernel 3: gather + format x -> g_A fragment layout ----------------
// block: (m16, e); 16 rows; two k-halves of 1024 each (32KB smem).
__global__ void format_A(const float* __restrict__ x) {
    __shared__ uint32_t sa[64 * 32 * 4];  // 32KB: [k16l(64)][lane][4 slots]
    const int m16 = blockIdx.x, e = blockIdx.y;
    const int cnt = g_counts[e];
    if (m16 * 16 >= cnt) return;
    const int t = threadIdx.x;
    const float4* x4 = reinterpret_cast<const float4*>(x);

    for (int half = 0; half < 2; half++) {
#pragma unroll
        for (int it = 0; it < 16; it++) {
            int lin = it * 256 + t;      // 0..4095
            int row = lin >> 8;          // 0..15
            int f4l = lin & 255;         // float4 within half
            int gr = m16 * 16 + row;
            int tok = (gr < cnt) ? g_tokens[e * N_TOKENS + gr] : -1;
            float4 v = make_float4(0.f, 0.f, 0.f, 0.f);
            if (tok >= 0) v = x4[(size_t)tok * 512 + half * 256 + f4l];
            int k16l = f4l >> 2;
            int lane0 = (row & 7) * 4 + 2 * (f4l & 1);
            int reg = ((row >> 3) & 1) + (((f4l >> 1) & 1) << 1);
            sa[((k16l * 32 + lane0) << 2) + reg] = h2u(__floats2half2_rn(v.x, v.y));
            sa[((k16l * 32 + lane0 + 1) << 2) + reg] = h2u(__floats2half2_rn(v.z, v.w));
        }
        __syncthreads();
        uint4* gdst = g_A + ((size_t)(e * 512 + m16) * NK16 + half * 64) * 32;
#pragma unroll
        for (int i = 0; i < 8; i++) {
            int lin = i * 256 + t;       // 0..2047
            gdst[lin] = reinterpret_cast<uint4*>(sa)[lin];
        }
        __syncthreads();
    }
}

// ---------------- kernel 4: grouped GEMM (fp16 mma.sync, cp.async pipeline) ----------------
__global__ void __launch_bounds__(256, 2)
moe_gemm(const float* __restrict__ be, float* __restrict__ out) {
    __shared__ uint4 sm[3 * 1024];  // 3 stages x (A 512 + B 512) uint4 = 48KB

    const int e = blockIdx.z;
    const int cnt = g_counts[e];
    const int m0 = blockIdx.x * 128;
    if (m0 >= cnt) return;
    const int n0 = blockIdx.y * 128;

    const int tid = threadIdx.x, lane = tid & 31, warp = tid >> 5;
    const int wm = warp >> 2, wn = warp & 3;  // 2 x 4 warps

    const uint4* Ab = g_A + (size_t)(e * 512 + (m0 >> 4)) * NK16 * 32;
    const uint4* Bb = g_B + (size_t)(e * 128 + (n0 >> 4)) * NK16 * 32;

    // staging: 2 A units + 2 B units per thread per stage (16B each)
    const int u0 = tid, u1 = tid + 256;
    const int s0 = u0 >> 5, s1 = u1 >> 5;  // slab 0..15 -> (x16l = slab>>1, k16l = slab&1)
    const size_t gA0 = ((size_t)(s0 >> 1) * NK16 + (s0 & 1)) * 32 + (u0 & 31);
    const size_t gA1 = ((size_t)(s1 >> 1) * NK16 + (s1 & 1)) * 32 + (u1 & 31);
    const uint32_t sbase = (uint32_t)__cvta_generic_to_shared(sm);

    float c[4][4][4];
#pragma unroll
    for (int mt = 0; mt < 4; mt++)
#pragma unroll
        for (int nt = 0; nt < 4; nt++)
#pragma unroll
            for (int i = 0; i < 4; i++) c[mt][nt][i] = 0.f;

#define ISSUE(stage, kc) do {                                                  \
    uint32_t sd = sbase + ((stage) * 1024) * 16;                               \
    CP16(sd + u0 * 16,          Ab + gA0 + (size_t)(kc) * 64);                 \
    CP16(sd + u1 * 16,          Ab + gA1 + (size_t)(kc) * 64);                 \
    CP16(sd + (512 + u0) * 16,  Bb + gA0 + (size_t)(kc) * 64);                 \
    CP16(sd + (512 + u1) * 16,  Bb + gA1 + (size_t)(kc) * 64);                 \
} while (0)

    ISSUE(0, 0); asm volatile("cp.async.commit_group;" ::: "memory");
    ISSUE(1, 1); asm volatile("cp.async.commit_group;" ::: "memory");

    for (int kc = 0; kc < NCHUNK; kc++) {
        asm volatile("cp.async.wait_group 1;" ::: "memory");
        __syncthreads();
        int ks = kc + 2;
        if (ks < NCHUNK) ISSUE(ks % 3, ks);
        asm volatile("cp.async.commit_group;" ::: "memory");

        const uint4* st = sm + (kc % 3) * 1024;
#pragma unroll
        for (int k16 = 0; k16 < 2; k16++) {
            uint4 av[4], bv[2];
#pragma unroll
            for (int mt = 0; mt < 4; mt++)
                av[mt] = st[((wm * 4 + mt) * 2 + k16) * 32 + lane];
#pragma unroll
            for (int h = 0; h < 2; h++)
                bv[h] = st[512 + ((wn * 2 + h) * 2 + k16) * 32 + lane];
#pragma unroll
            for (int mt = 0; mt < 4; mt++)
#pragma unroll
                for (int h = 0; h < 2; h++) {
                    mma16816(c[mt][h * 2 + 0], av[mt], bv[h].x, bv[h].y);
                    mma16816(c[mt][h * 2 + 1], av[mt], bv[h].z, bv[h].w);
                }
        }
    }

    // ---------------- epilogue: out[tok] += w * (acc + be[e]) ----------------
    const float* bee = be + (size_t)e * HIDDEN + n0;
    const int r = lane >> 2, q = lane & 3;
    float bias[4][2];
#pragma unroll
    for (int nt = 0; nt < 4; nt++) {
        int col = wn * 32 + nt * 8 + 2 * q;
        bias[nt][0] = bee[col];
        bias[nt][1] = bee[col + 1];
    }
#pragma unroll
    for (int mt = 0; mt < 4; mt++)
#pragma unroll
        for (int rh = 0; rh < 2; rh++) {
            int gr = m0 + wm * 64 + mt * 16 + r + rh * 8;
            if (gr < cnt) {
                int tok = g_tokens[e * N_TOKENS + gr];
                float w = g_wts[e * N_TOKENS + gr];
                float* orow = out + (size_t)tok * HIDDEN + n0;
#pragma unroll
                for (int nt = 0; nt < 4; nt++) {
                    int col = wn * 32 + nt * 8 + 2 * q;
                    float v0 = w * (c[mt][nt][rh * 2 + 0] + bias[nt][0]);
                    float v1 = w * (c[mt][nt][rh * 2 + 1] + bias[nt][1]);
                    asm volatile("red.global.add.v2.f32 [%0], {%1,%2};"
                                 :: "l"(orow + col), "f"(v0), "f"(v1) : "memory");
                }
            }
        }
}

// ---------------- launch ----------------
extern "C" void kernel_launch(void* const* d_in, const int* in_sizes, int n_in,
                              void* d_out, int out_size) {
    const float* x  = (const float*)d_in[0];
    const float* Wg = (const float*)d_in[1];
    const float* bg = (const float*)d_in[2];
    const float* We = (const float*)d_in[3];
    const float* be = (const float*)d_in[4];
    float* out = (float*)d_out;

    zero_kernel<<<2048, 256>>>(out, out_size / 4);
    gating_kernel<<<N_TOKENS / 8, 256>>>(x, Wg, bg);
    format_B<<<dim3(HIDDEN / 64, D_IN / 128, N_EXPERTS), 256>>>(We);
    format_A<<<dim3(512, N_EXPERTS), 256>>>(x);
    moe_gemm<<<dim3(64, HIDDEN / 128, N_EXPERTS), 256>>>(be, out);
}